// round 2
// baseline (speedup 1.0000x reference)
#include <cuda_runtime.h>
#include <cstdint>

#define NT 4
#define NR 768
#define NOUT 64
#define WROWS 89   // 88 real feature rows + 1 zero row (index 88) for "no bin"

// Scratch (no cudaMalloc allowed): per-residue derived data + transposed weights.
// Per residue (20 floats): M[9] (rigid rot, row-major, rigid_vec = M * diff),
// ca[3], pb[3], fm, pbm, aj_off(int bits), pad, pad
__device__ float d_res[NT * NR * 20];
__device__ __align__(16) float d_wt[WROWS * NOUT];

// ---------------------------------------------------------------------------
// Kernel 0a: transpose linear_w [64][88] -> d_wt[89][64], zero row 88
// ---------------------------------------------------------------------------
__global__ void prep_w(const float* __restrict__ w) {
    int idx = blockIdx.x * blockDim.x + threadIdx.x;
    if (idx >= WROWS * NOUT) return;
    int c = idx >> 6;          // feature row 0..88
    int o = idx & 63;          // output channel
    d_wt[c * NOUT + o] = (c < 88) ? w[o * 88 + c] : 0.0f;
}

// ---------------------------------------------------------------------------
// Kernel 0b: per-residue rigid frame + feature pack
// ---------------------------------------------------------------------------
__global__ void prep_res(const float* __restrict__ pos,   // [NT][NR][37][3]
                         const float* __restrict__ tpb,   // [NT][NR][3]
                         const float* __restrict__ pbm,   // [NT][NR]
                         const float* __restrict__ aam,   // [NT][NR][37]
                         const int*   __restrict__ aatype)// [NT][NR]
{
    int idx = blockIdx.x * blockDim.x + threadIdx.x;
    if (idx >= NT * NR) return;

    const float* p = pos + (size_t)idx * 37 * 3;
    float nx = p[0], ny = p[1], nz = p[2];    // N
    float cax = p[3], cay = p[4], caz = p[5]; // CA
    float cx = p[6], cy = p[7], cz = p[8];    // C

    // translate so CA at origin
    nx -= cax; ny -= cay; nz -= caz;
    cx -= cax; cy -= cay; cz -= caz;

    const float eps = 1e-6f;
    float n1 = sqrtf(eps + cx * cx + cy * cy);
    float s1 = -cy / n1, c1 = cx / n1;
    float n2 = sqrtf(eps + cx * cx + cy * cy + cz * cz);
    float s2 = cz / n2;
    float c2v = sqrtf(cx * cx + cy * cy) / n2;

    // c_rots = c2 @ c1
    float r00 = c2v * c1, r01 = -c2v * s1, r02 = s2;
    float r10 = s1,       r11 = c1,        r12 = 0.0f;
    float r20 = -s2 * c1, r21 = s2 * s1,   r22 = c2v;

    // n_rot = c_rots @ n  (need components 1 and 2)
    float nr1 = r10 * nx + r11 * ny + r12 * nz;
    float nr2 = r20 * nx + r21 * ny + r22 * nz;
    float n3 = sqrtf(eps + nr1 * nr1 + nr2 * nr2);
    float sn = -nr2 / n3, cn = nr1 / n3;

    // M = nr @ c_rots ; rots (reference) = M^T ; rigid_vec = M @ diff
    float* q = d_res + (size_t)idx * 20;
    q[0] = r00;                 q[1] = r01;                 q[2] = r02;
    q[3] = cn * r10 - sn * r20; q[4] = cn * r11 - sn * r21; q[5] = cn * r12 - sn * r22;
    q[6] = sn * r10 + cn * r20; q[7] = sn * r11 + cn * r21; q[8] = sn * r12 + cn * r22;
    q[9]  = cax; q[10] = cay; q[11] = caz;

    const float* pb = tpb + (size_t)idx * 3;
    q[12] = pb[0]; q[13] = pb[1]; q[14] = pb[2];

    const float* am = aam + (size_t)idx * 37;
    q[15] = am[0] * am[1] * am[2];  // frame mask
    q[16] = pbm[idx];               // pseudo-beta mask
    int aj = aatype[idx];
    q[17] = __int_as_float((40 + aj) * NOUT);  // oh_j column offset (elements)
    q[18] = 0.0f; q[19] = 0.0f;
}

// ---------------------------------------------------------------------------
// Main kernel: one block per (t, i); 256 threads.
// Phase A: per-j scalars into smem. Phase B: 16 j-slots x 16 o-quads.
// ---------------------------------------------------------------------------
__global__ __launch_bounds__(256) void pair_kernel(const float* __restrict__ bias,
                                                   float* __restrict__ out)
{
    const int i = blockIdx.x;
    const int t = blockIdx.y;

    __shared__ float  si[20];
    __shared__ float4 s0[NR];  // ux, uy, uz, fm2
    __shared__ float4 s1[NR];  // pbm2, bin_off(bits), aj_off(bits), -

    const float* resb = d_res + (size_t)t * NR * 20;
    if (threadIdx.x < 20) si[threadIdx.x] = resb[(size_t)i * 20 + threadIdx.x];
    __syncthreads();

    const float m0 = si[0], m1 = si[1], m2 = si[2];
    const float m3 = si[3], m4 = si[4], m5 = si[5];
    const float m6 = si[6], m7 = si[7], m8 = si[8];
    const float cax = si[9], cay = si[10], caz = si[11];
    const float pbx = si[12], pby = si[13], pbz = si[14];
    const float fmi = si[15], pbmi = si[16];
    const int   aioff = __float_as_int(si[17]) + 22 * NOUT;  // oh_i column

    // ---- Phase A: per-j pair scalars ----
    for (int j = threadIdx.x; j < NR; j += 256) {
        const float* rj = resb + (size_t)j * 20;
        // distogram bin from pseudo-beta distance
        float dx = rj[12] - pbx, dy = rj[13] - pby, dz = rj[14] - pbz;
        float d2 = __fadd_rn(__fadd_rn(__fmul_rn(dx, dx), __fmul_rn(dy, dy)),
                             __fmul_rn(dz, dz));
        int bin = -1;
        {
            float r = sqrtf(d2);
            int k0 = (int)floorf((r - 3.25f) * 0.8f);
            k0 = max(0, min(38, k0));
            #pragma unroll
            for (int dk = -1; dk <= 1; dk++) {
                int kk = k0 + dk;
                if (kk < 0 || kk > 38) continue;
                float lo = 3.25f + 1.25f * (float)kk; lo = lo * lo;
                float hi;
                if (kk == 38) hi = 1e8f;
                else { hi = 3.25f + 1.25f * (float)(kk + 1); hi = hi * hi; }
                if (d2 > lo && d2 < hi) bin = kk;
            }
        }
        // rigid vec: v = M * (ca_j - ca_i)
        float ddx = rj[9] - cax, ddy = rj[10] - cay, ddz = rj[11] - caz;
        float vx = m0 * ddx + m1 * ddy + m2 * ddz;
        float vy = m3 * ddx + m4 * ddy + m5 * ddz;
        float vz = m6 * ddx + m7 * ddy + m8 * ddz;
        float inv = rsqrtf(1e-6f + vx * vx + vy * vy + vz * vz);

        float fm2  = fmi * rj[15];
        float pbm2 = pbmi * rj[16];
        int binoff = (bin >= 0 ? bin : 88) * NOUT;

        s0[j] = make_float4(vx * inv, vy * inv, vz * inv, fm2);
        s1[j] = make_float4(pbm2, __int_as_float(binoff), rj[17], 0.0f);
    }
    __syncthreads();

    // ---- Phase B ----
    const int og = threadIdx.x & 15;     // o-quad 0..15
    const int js = threadIdx.x >> 4;     // j-slot 0..15
    const int o4 = og * 4;

    const float4 w39 = *(const float4*)(d_wt + 39 * NOUT + o4);
    const float4 w84 = *(const float4*)(d_wt + 84 * NOUT + o4);
    const float4 w85 = *(const float4*)(d_wt + 85 * NOUT + o4);
    const float4 w86 = *(const float4*)(d_wt + 86 * NOUT + o4);
    const float4 wai = *(const float4*)(d_wt + aioff + o4);
    const float4 w87 = *(const float4*)(d_wt + 87 * NOUT + o4);
    float4 colI;
    colI.x = wai.x + w87.x; colI.y = wai.y + w87.y;
    colI.z = wai.z + w87.z; colI.w = wai.w + w87.w;
    const float4 b4 = *(const float4*)(bias + o4);

    float* obase = out + (((size_t)t * NR + i) * NR) * NOUT;

    #pragma unroll 4
    for (int it = 0; it < NR / 16; ++it) {
        int j = it * 16 + js;
        float4 a  = s0[j];
        float4 mm = s1[j];
        const float4 wb = *(const float4*)(d_wt + __float_as_int(mm.y) + o4);
        const float4 wa = *(const float4*)(d_wt + __float_as_int(mm.z) + o4);
        float4 r;
        r.x = wb.x + wa.x + colI.x;
        r.y = wb.y + wa.y + colI.y;
        r.z = wb.z + wa.z + colI.z;
        r.w = wb.w + wa.w + colI.w;
        r.x = fmaf(mm.x, w39.x, r.x); r.y = fmaf(mm.x, w39.y, r.y);
        r.z = fmaf(mm.x, w39.z, r.z); r.w = fmaf(mm.x, w39.w, r.w);
        r.x = fmaf(a.x, w84.x, r.x);  r.y = fmaf(a.x, w84.y, r.y);
        r.z = fmaf(a.x, w84.z, r.z);  r.w = fmaf(a.x, w84.w, r.w);
        r.x = fmaf(a.y, w85.x, r.x);  r.y = fmaf(a.y, w85.y, r.y);
        r.z = fmaf(a.y, w85.z, r.z);  r.w = fmaf(a.y, w85.w, r.w);
        r.x = fmaf(a.z, w86.x, r.x);  r.y = fmaf(a.z, w86.y, r.y);
        r.z = fmaf(a.z, w86.z, r.z);  r.w = fmaf(a.z, w86.w, r.w);
        r.x = fmaf(a.w, r.x, b4.x);   r.y = fmaf(a.w, r.y, b4.y);
        r.z = fmaf(a.w, r.z, b4.z);   r.w = fmaf(a.w, r.w, b4.w);
        *(float4*)(obase + (size_t)j * NOUT + o4) = r;
    }
}

// ---------------------------------------------------------------------------
extern "C" void kernel_launch(void* const* d_in, const int* in_sizes, int n_in,
                              void* d_out, int out_size)
{
    const float* pos    = (const float*)d_in[0];
    const float* tpb    = (const float*)d_in[1];
    const float* pbmask = (const float*)d_in[2];
    const float* aam    = (const float*)d_in[3];
    const int*   aatype = (const int*)  d_in[4];
    const float* w      = (const float*)d_in[5];
    const float* b      = (const float*)d_in[6];
    float* out = (float*)d_out;

    prep_w<<<(WROWS * NOUT + 255) / 256, 256>>>(w);
    prep_res<<<(NT * NR + 127) / 128, 128>>>(pos, tpb, pbmask, aam, aatype);
    dim3 grid(NR, NT);
    pair_kernel<<<grid, 256>>>(b, out);
}

// round 3
// speedup vs baseline: 1.0076x; 1.0076x over previous
#include <cuda_runtime.h>
#include <cstdint>

#define NT 4
#define NR 768
#define NOUT 64
#define WROWS 89   // 88 real feature rows + 1 zero row (index 88) for "no bin"

// Scratch (no cudaMalloc allowed): per-residue derived data + transposed weights.
// Per residue (20 floats): M[9] (rigid rot, row-major, rigid_vec = M * diff),
// ca[3], pb[3], fm, pbm, aj_off(int bits), pad, pad
__device__ float d_res[NT * NR * 20];
__device__ __align__(16) float d_wt[WROWS * NOUT];

// ---------------------------------------------------------------------------
// Kernel 0a: transpose linear_w [64][88] -> d_wt[89][64], zero row 88
// ---------------------------------------------------------------------------
__global__ void prep_w(const float* __restrict__ w) {
    int idx = blockIdx.x * blockDim.x + threadIdx.x;
    if (idx >= WROWS * NOUT) return;
    int c = idx >> 6;          // feature row 0..88
    int o = idx & 63;          // output channel
    d_wt[c * NOUT + o] = (c < 88) ? w[o * 88 + c] : 0.0f;
}

// ---------------------------------------------------------------------------
// Kernel 0b: per-residue rigid frame + feature pack
// ---------------------------------------------------------------------------
__global__ void prep_res(const float* __restrict__ pos,   // [NT][NR][37][3]
                         const float* __restrict__ tpb,   // [NT][NR][3]
                         const float* __restrict__ pbm,   // [NT][NR]
                         const float* __restrict__ aam,   // [NT][NR][37]
                         const int*   __restrict__ aatype)// [NT][NR]
{
    int idx = blockIdx.x * blockDim.x + threadIdx.x;
    if (idx >= NT * NR) return;

    const float* p = pos + (size_t)idx * 37 * 3;
    float nx = p[0], ny = p[1], nz = p[2];    // N
    float cax = p[3], cay = p[4], caz = p[5]; // CA
    float cx = p[6], cy = p[7], cz = p[8];    // C

    // translate so CA at origin
    nx -= cax; ny -= cay; nz -= caz;
    cx -= cax; cy -= cay; cz -= caz;

    const float eps = 1e-6f;
    float n1 = sqrtf(eps + cx * cx + cy * cy);
    float s1 = -cy / n1, c1 = cx / n1;
    float n2 = sqrtf(eps + cx * cx + cy * cy + cz * cz);
    float s2 = cz / n2;
    float c2v = sqrtf(cx * cx + cy * cy) / n2;

    // c_rots = c2 @ c1
    float r00 = c2v * c1, r01 = -c2v * s1, r02 = s2;
    float r10 = s1,       r11 = c1,        r12 = 0.0f;
    float r20 = -s2 * c1, r21 = s2 * s1,   r22 = c2v;

    // n_rot = c_rots @ n  (need components 1 and 2)
    float nr1 = r10 * nx + r11 * ny + r12 * nz;
    float nr2 = r20 * nx + r21 * ny + r22 * nz;
    float n3 = sqrtf(eps + nr1 * nr1 + nr2 * nr2);
    float sn = -nr2 / n3, cn = nr1 / n3;

    // M = nr @ c_rots ; rots (reference) = M^T ; rigid_vec = M @ diff
    float* q = d_res + (size_t)idx * 20;
    q[0] = r00;                 q[1] = r01;                 q[2] = r02;
    q[3] = cn * r10 - sn * r20; q[4] = cn * r11 - sn * r21; q[5] = cn * r12 - sn * r22;
    q[6] = sn * r10 + cn * r20; q[7] = sn * r11 + cn * r21; q[8] = sn * r12 + cn * r22;
    q[9]  = cax; q[10] = cay; q[11] = caz;

    const float* pb = tpb + (size_t)idx * 3;
    q[12] = pb[0]; q[13] = pb[1]; q[14] = pb[2];

    const float* am = aam + (size_t)idx * 37;
    q[15] = am[0] * am[1] * am[2];  // frame mask
    q[16] = pbm[idx];               // pseudo-beta mask
    int aj = aatype[idx];
    q[17] = __int_as_float((40 + aj) * NOUT);  // oh_j column offset (elements)
    q[18] = 0.0f; q[19] = 0.0f;
}

// ---------------------------------------------------------------------------
// Main kernel: one block per (t, i); 256 threads.
// Phase A: per-j scalars into smem. Phase B: 16 j-slots x 16 o-quads.
// ---------------------------------------------------------------------------
__global__ __launch_bounds__(256) void pair_kernel(const float* __restrict__ bias,
                                                   float* __restrict__ out)
{
    const int i = blockIdx.x;
    const int t = blockIdx.y;

    __shared__ float  si[20];
    __shared__ float4 s0[NR];  // ux, uy, uz, fm2
    __shared__ float4 s1[NR];  // pbm2, bin_off(bits), aj_off(bits), -

    const float* resb = d_res + (size_t)t * NR * 20;
    if (threadIdx.x < 20) si[threadIdx.x] = resb[(size_t)i * 20 + threadIdx.x];
    __syncthreads();

    const float m0 = si[0], m1 = si[1], m2 = si[2];
    const float m3 = si[3], m4 = si[4], m5 = si[5];
    const float m6 = si[6], m7 = si[7], m8 = si[8];
    const float cax = si[9], cay = si[10], caz = si[11];
    const float pbx = si[12], pby = si[13], pbz = si[14];
    const float fmi = si[15], pbmi = si[16];
    const int   aioff = __float_as_int(si[17]) + 22 * NOUT;  // oh_i column

    // ---- Phase A: per-j pair scalars ----
    for (int j = threadIdx.x; j < NR; j += 256) {
        const float* rj = resb + (size_t)j * 20;
        // distogram bin from pseudo-beta distance
        float dx = rj[12] - pbx, dy = rj[13] - pby, dz = rj[14] - pbz;
        float d2 = __fadd_rn(__fadd_rn(__fmul_rn(dx, dx), __fmul_rn(dy, dy)),
                             __fmul_rn(dz, dz));
        int bin = -1;
        {
            float r = sqrtf(d2);
            int k0 = (int)floorf((r - 3.25f) * 0.8f);
            k0 = max(0, min(38, k0));
            #pragma unroll
            for (int dk = -1; dk <= 1; dk++) {
                int kk = k0 + dk;
                if (kk < 0 || kk > 38) continue;
                float lo = 3.25f + 1.25f * (float)kk; lo = lo * lo;
                float hi;
                if (kk == 38) hi = 1e8f;
                else { hi = 3.25f + 1.25f * (float)(kk + 1); hi = hi * hi; }
                if (d2 > lo && d2 < hi) bin = kk;
            }
        }
        // rigid vec: v = M * (ca_j - ca_i)
        float ddx = rj[9] - cax, ddy = rj[10] - cay, ddz = rj[11] - caz;
        float vx = m0 * ddx + m1 * ddy + m2 * ddz;
        float vy = m3 * ddx + m4 * ddy + m5 * ddz;
        float vz = m6 * ddx + m7 * ddy + m8 * ddz;
        float inv = rsqrtf(1e-6f + vx * vx + vy * vy + vz * vz);

        float fm2  = fmi * rj[15];
        float pbm2 = pbmi * rj[16];
        int binoff = (bin >= 0 ? bin : 88) * NOUT;

        s0[j] = make_float4(vx * inv, vy * inv, vz * inv, fm2);
        s1[j] = make_float4(pbm2, __int_as_float(binoff), rj[17], 0.0f);
    }
    __syncthreads();

    // ---- Phase B ----
    const int og = threadIdx.x & 15;     // o-quad 0..15
    const int js = threadIdx.x >> 4;     // j-slot 0..15
    const int o4 = og * 4;

    const float4 w39 = *(const float4*)(d_wt + 39 * NOUT + o4);
    const float4 w84 = *(const float4*)(d_wt + 84 * NOUT + o4);
    const float4 w85 = *(const float4*)(d_wt + 85 * NOUT + o4);
    const float4 w86 = *(const float4*)(d_wt + 86 * NOUT + o4);
    const float4 wai = *(const float4*)(d_wt + aioff + o4);
    const float4 w87 = *(const float4*)(d_wt + 87 * NOUT + o4);
    float4 colI;
    colI.x = wai.x + w87.x; colI.y = wai.y + w87.y;
    colI.z = wai.z + w87.z; colI.w = wai.w + w87.w;
    const float4 b4 = *(const float4*)(bias + o4);

    float* obase = out + (((size_t)t * NR + i) * NR) * NOUT;

    #pragma unroll 4
    for (int it = 0; it < NR / 16; ++it) {
        int j = it * 16 + js;
        float4 a  = s0[j];
        float4 mm = s1[j];
        const float4 wb = *(const float4*)(d_wt + __float_as_int(mm.y) + o4);
        const float4 wa = *(const float4*)(d_wt + __float_as_int(mm.z) + o4);
        float4 r;
        r.x = wb.x + wa.x + colI.x;
        r.y = wb.y + wa.y + colI.y;
        r.z = wb.z + wa.z + colI.z;
        r.w = wb.w + wa.w + colI.w;
        r.x = fmaf(mm.x, w39.x, r.x); r.y = fmaf(mm.x, w39.y, r.y);
        r.z = fmaf(mm.x, w39.z, r.z); r.w = fmaf(mm.x, w39.w, r.w);
        r.x = fmaf(a.x, w84.x, r.x);  r.y = fmaf(a.x, w84.y, r.y);
        r.z = fmaf(a.x, w84.z, r.z);  r.w = fmaf(a.x, w84.w, r.w);
        r.x = fmaf(a.y, w85.x, r.x);  r.y = fmaf(a.y, w85.y, r.y);
        r.z = fmaf(a.y, w85.z, r.z);  r.w = fmaf(a.y, w85.w, r.w);
        r.x = fmaf(a.z, w86.x, r.x);  r.y = fmaf(a.z, w86.y, r.y);
        r.z = fmaf(a.z, w86.z, r.z);  r.w = fmaf(a.z, w86.w, r.w);
        r.x = fmaf(a.w, r.x, b4.x);   r.y = fmaf(a.w, r.y, b4.y);
        r.z = fmaf(a.w, r.z, b4.z);   r.w = fmaf(a.w, r.w, b4.w);
        *(float4*)(obase + (size_t)j * NOUT + o4) = r;
    }
}

// ---------------------------------------------------------------------------
extern "C" void kernel_launch(void* const* d_in, const int* in_sizes, int n_in,
                              void* d_out, int out_size)
{
    const float* pos    = (const float*)d_in[0];
    const float* tpb    = (const float*)d_in[1];
    const float* pbmask = (const float*)d_in[2];
    const float* aam    = (const float*)d_in[3];
    const int*   aatype = (const int*)  d_in[4];
    const float* w      = (const float*)d_in[5];
    const float* b      = (const float*)d_in[6];
    float* out = (float*)d_out;

    prep_w<<<(WROWS * NOUT + 255) / 256, 256>>>(w);
    prep_res<<<(NT * NR + 127) / 128, 128>>>(pos, tpb, pbmask, aam, aatype);
    dim3 grid(NR, NT);
    pair_kernel<<<grid, 256>>>(b, out);
}